// round 1
// baseline (speedup 1.0000x reference)
#include <cuda_runtime.h>
#include <math.h>

// ---------------- scratch (static device globals; no runtime alloc) ----------
// qkv: [B=2, N=2048, 3C=3072] fp32
__device__ float g_qkv[2 * 2048 * 3072];
// attention output (pre-proj): [B, N, C=1024]
__device__ float g_att[2 * 2048 * 1024];
// V row-sums per (b,h): [B*H, Dh=64]
__device__ float g_vsum[2 * 16 * 64];

// ---------------- SGEMM: C[m,n] = sum_k A[m,k] * B[n,k] (+ bias[n]) ----------
// A: [M,K] row-major, B: [N,K] row-major (i.e., C = A * B^T). M,N %128==0, K%8==0.
#define BM 128
#define BN 128
#define BKK 8
#define TM 8
#define TN 8

__global__ __launch_bounds__(256, 2)
void gemm_nt(const float* __restrict__ A, const float* __restrict__ B,
             const float* __restrict__ bias, float* __restrict__ C,
             int M, int N, int K) {
    __shared__ float As[BKK][BM];
    __shared__ float Bs[BKK][BN];

    const int tid = threadIdx.x;            // 256 threads
    const int bm  = blockIdx.y * BM;
    const int bn  = blockIdx.x * BN;
    const int tx  = tid & 15;               // 16 cols of threads
    const int ty  = tid >> 4;               // 16 rows of threads

    const int lr = tid >> 1;                // load row 0..127
    const int lc = (tid & 1) * 4;           // load col 0 or 4

    const float* Ab = A + (size_t)bm * K;
    const float* Bb = B + (size_t)bn * K;

    float acc[TM][TN];
    #pragma unroll
    for (int i = 0; i < TM; i++)
        #pragma unroll
        for (int j = 0; j < TN; j++) acc[i][j] = 0.0f;

    for (int k0 = 0; k0 < K; k0 += BKK) {
        float4 a4 = *reinterpret_cast<const float4*>(Ab + (size_t)lr * K + k0 + lc);
        float4 b4 = *reinterpret_cast<const float4*>(Bb + (size_t)lr * K + k0 + lc);
        As[lc + 0][lr] = a4.x; As[lc + 1][lr] = a4.y;
        As[lc + 2][lr] = a4.z; As[lc + 3][lr] = a4.w;
        Bs[lc + 0][lr] = b4.x; Bs[lc + 1][lr] = b4.y;
        Bs[lc + 2][lr] = b4.z; Bs[lc + 3][lr] = b4.w;
        __syncthreads();

        #pragma unroll
        for (int k = 0; k < BKK; k++) {
            float ra[TM], rb[TN];
            float4 t0 = *reinterpret_cast<const float4*>(&As[k][ty * TM]);
            float4 t1 = *reinterpret_cast<const float4*>(&As[k][ty * TM + 4]);
            ra[0]=t0.x; ra[1]=t0.y; ra[2]=t0.z; ra[3]=t0.w;
            ra[4]=t1.x; ra[5]=t1.y; ra[6]=t1.z; ra[7]=t1.w;
            float4 u0 = *reinterpret_cast<const float4*>(&Bs[k][tx * TN]);
            float4 u1 = *reinterpret_cast<const float4*>(&Bs[k][tx * TN + 4]);
            rb[0]=u0.x; rb[1]=u0.y; rb[2]=u0.z; rb[3]=u0.w;
            rb[4]=u1.x; rb[5]=u1.y; rb[6]=u1.z; rb[7]=u1.w;
            #pragma unroll
            for (int i = 0; i < TM; i++)
                #pragma unroll
                for (int j = 0; j < TN; j++)
                    acc[i][j] = fmaf(ra[i], rb[j], acc[i][j]);
        }
        __syncthreads();
    }

    #pragma unroll
    for (int i = 0; i < TM; i++) {
        const int row = bm + ty * TM + i;
        float* Cr = C + (size_t)row * N + bn + tx * TN;
        #pragma unroll
        for (int j = 0; j < TN; j += 4) {
            float4 o;
            o.x = acc[i][j + 0]; o.y = acc[i][j + 1];
            o.z = acc[i][j + 2]; o.w = acc[i][j + 3];
            if (bias) {
                const float* bp = bias + bn + tx * TN + j;
                o.x += bp[0]; o.y += bp[1]; o.z += bp[2]; o.w += bp[3];
            }
            *reinterpret_cast<float4*>(Cr + j) = o;
        }
    }
}

// ---------------- V row-sum: S[b,h,dh] = sum_n v[b,h,n,dh] ------------------
__global__ void vsum_kernel() {
    const int N = 2048, C3 = 3072, Dh = 64, H = 16;
    const int bh = blockIdx.x;         // 0..31
    const int b = bh / H, h = bh % H;
    const int dh = threadIdx.x;        // 0..63
    const float* base = g_qkv + (size_t)(b * N) * C3 + 2048 + h * Dh + dh;
    float s = 0.0f;
    for (int n = 0; n < N; n++) s += base[(size_t)n * C3];
    g_vsum[bh * Dh + dh] = s;
}

// ---------------- banded attention (one warp per (b,h,n)) -------------------
// Exploits: masked logits are all 1e-9 -> constant weight; use V row-sums.
__global__ void band_attn(const int* __restrict__ epoch_p) {
    const int N = 2048, H = 16, Dh = 64, C3 = 3072;
    const int w = (*epoch_p < 15) ? 16 : 20;

    const int warp = (blockIdx.x * blockDim.x + threadIdx.x) >> 5;
    const int lane = threadIdx.x & 31;
    if (warp >= 2 * H * N) return;

    const int n  = warp % N;
    const int bh = warp / N;
    const int b  = bh / H, h = bh % H;

    const float* qp = g_qkv + (size_t)(b * N + n) * C3 + h * Dh;
    const float q0 = qp[lane], q1 = qp[lane + 32];

    const int m0 = max(0, n - w);
    const int m1 = min(N - 1, n + w);

    float Mx = -INFINITY, Z = 0.0f;
    float a0 = 0.0f, a1 = 0.0f, bv0 = 0.0f, bv1 = 0.0f;

    for (int m = m0; m <= m1; m++) {
        const float* kp = g_qkv + (size_t)(b * N + m) * C3 + 1024 + h * Dh;
        const float k0 = kp[lane], k1 = kp[lane + 32];
        const float v0 = kp[1024 + lane], v1 = kp[1024 + lane + 32];

        float p = q0 * k0 + q1 * k1;
        p += __shfl_xor_sync(0xffffffffu, p, 16);
        p += __shfl_xor_sync(0xffffffffu, p, 8);
        p += __shfl_xor_sync(0xffffffffu, p, 4);
        p += __shfl_xor_sync(0xffffffffu, p, 2);
        p += __shfl_xor_sync(0xffffffffu, p, 1);
        const float l = p * 4.0f;    // scale = Dh // H = 4

        if (l > Mx) {
            const float f = expf(Mx - l);   // Mx=-inf -> 0
            Z *= f; a0 *= f; a1 *= f;
            Mx = l;
        }
        const float e = expf(l - Mx);
        Z += e;
        a0 = fmaf(e, v0, a0);
        a1 = fmaf(e, v1, a1);
        bv0 += v0; bv1 += v1;
    }

    // masked entries: value 1e-9, count N - n_band
    float lm = 1e-9f;
    if (lm > Mx) {                       // defensive; essentially never
        const float f = expf(Mx - lm);
        Z *= f; a0 *= f; a1 *= f;
        Mx = lm;
    }
    const float cu = expf(lm - Mx);
    const int nband = m1 - m0 + 1;
    Z += (float)(N - nband) * cu;

    const float s0 = g_vsum[bh * Dh + lane];
    const float s1 = g_vsum[bh * Dh + lane + 32];
    const float invZ = 1.0f / Z;
    const float o0 = (a0 + cu * (s0 - bv0)) * invZ;
    const float o1 = (a1 + cu * (s1 - bv1)) * invZ;

    float* op = g_att + (size_t)(b * N + n) * 1024 + h * Dh;
    op[lane]      = o0;
    op[lane + 32] = o1;
}

// ---------------- launcher ---------------------------------------------------
extern "C" void kernel_launch(void* const* d_in, const int* in_sizes, int n_in,
                              void* d_out, int out_size) {
    const float* x      = (const float*)d_in[0];   // [2,2048,1024]
    const float* qkv_w  = (const float*)d_in[1];   // [3072,1024]
    const float* proj_w = (const float*)d_in[2];   // [1024,1024]
    const float* proj_b = (const float*)d_in[3];   // [1024]
    const int*   epoch  = (const int*)d_in[4];     // scalar

    float* qkv_buf; float* att_buf;
    cudaGetSymbolAddress((void**)&qkv_buf, g_qkv);
    cudaGetSymbolAddress((void**)&att_buf, g_att);

    const int M = 2 * 2048;       // 4096
    const int K = 1024;

    // 1) qkv = x @ qkv_w^T   -> [4096, 3072]
    {
        dim3 grid(3072 / BN, M / BM);
        gemm_nt<<<grid, 256>>>(x, qkv_w, nullptr, qkv_buf, M, 3072, K);
    }

    // 2) per-(b,h) V row sums
    vsum_kernel<<<32, 64>>>();

    // 3) banded attention -> g_att [4096, 1024]
    {
        const int total_warps = 2 * 16 * 2048;      // 65536
        const int threads = 256;                    // 8 warps/block
        band_attn<<<total_warps / 8, threads>>>(epoch);
    }

    // 4) out = att @ proj_w^T + proj_b -> d_out [4096, 1024]
    {
        dim3 grid(1024 / BN, M / BM);
        gemm_nt<<<grid, 256>>>(att_buf, proj_w, proj_b, (float*)d_out, M, 1024, K);
    }
}

// round 3
// speedup vs baseline: 1.3413x; 1.3413x over previous
#include <cuda_runtime.h>
#include <cstdint>
#include <math.h>

// ---------------- scratch (static device globals; no runtime alloc) ----------
__device__ float g_qkv[2 * 2048 * 3072];        // [B,N,3C]
__device__ float g_att[2 * 2048 * 1024];        // [B,N,C]
__device__ float g_vsum[2 * 16 * 64];           // [BH, Dh]
__device__ float g_vsum_p[2 * 16 * 16 * 64];    // [BH, 16 slices, Dh]

// ---------------- 3xTF32 tensor-core GEMM:  C = A * B^T (+bias) --------------
// A: [M,K] row-major, B: [N,K] row-major. M%128==0, N%128==0, K%16==0.
#define LDSP 20   // padded smem row stride in floats (conflict-free frag reads)

__device__ __forceinline__ void cp_async16(void* smem, const void* gmem) {
    uint32_t s = (uint32_t)__cvta_generic_to_shared(smem);
    asm volatile("cp.async.ca.shared.global [%0], [%1], 16;" :: "r"(s), "l"(gmem));
}
__device__ __forceinline__ uint32_t cvt_tf32(float x) {
    uint32_t u; asm("cvt.rna.tf32.f32 %0, %1;" : "=r"(u) : "f"(x)); return u;
}
// split x into tf32 hi + tf32 lo (3xTF32 scheme)
__device__ __forceinline__ void split_tf32(float x, uint32_t& hi, uint32_t& lo) {
    hi = cvt_tf32(x);
    lo = cvt_tf32(x - __uint_as_float(hi));
}
__device__ __forceinline__ void mma_tf32(float* c, const uint32_t* a, const uint32_t* b) {
    asm volatile(
        "mma.sync.aligned.m16n8k8.row.col.f32.tf32.tf32.f32 "
        "{%0,%1,%2,%3}, {%4,%5,%6,%7}, {%8,%9}, {%0,%1,%2,%3};"
        : "+f"(c[0]), "+f"(c[1]), "+f"(c[2]), "+f"(c[3])
        : "r"(a[0]), "r"(a[1]), "r"(a[2]), "r"(a[3]), "r"(b[0]), "r"(b[1]));
}

__global__ __launch_bounds__(256)
void gemm_3xtf32(const float* __restrict__ A, const float* __restrict__ B,
                 const float* __restrict__ bias, float* __restrict__ C,
                 int M, int N, int K) {
    __shared__ float As[2][128 * LDSP];
    __shared__ float Bs[2][128 * LDSP];

    const int tid = threadIdx.x;
    const int lane = tid & 31;
    const int wid = tid >> 5;
    const int warp_m = wid & 1;    // 0..1  (64 rows each)
    const int warp_n = wid >> 1;   // 0..3  (32 cols each)
    const int bm = blockIdx.y * 128;
    const int bn = blockIdx.x * 128;
    const int gr = lane >> 2;      // 0..7
    const int gc = lane & 3;       // 0..3

    float acc[4][4][4];
    #pragma unroll
    for (int i = 0; i < 4; i++)
        #pragma unroll
        for (int j = 0; j < 4; j++)
            #pragma unroll
            for (int r = 0; r < 4; r++) acc[i][j][r] = 0.0f;

    const int niter = K >> 4;   // K/16

    auto load_stage = [&](int st, int k0) {
        #pragma unroll
        for (int r = 0; r < 2; r++) {
            const int idx = tid + 256 * r;
            const int row = idx >> 2;
            const int c4 = (idx & 3) * 4;
            cp_async16(&As[st][row * LDSP + c4], A + (size_t)(bm + row) * K + k0 + c4);
            cp_async16(&Bs[st][row * LDSP + c4], B + (size_t)(bn + row) * K + k0 + c4);
        }
        asm volatile("cp.async.commit_group;");
    };

    load_stage(0, 0);

    for (int kt = 0; kt < niter; kt++) {
        if (kt + 1 < niter) {
            load_stage((kt + 1) & 1, (kt + 1) * 16);
            asm volatile("cp.async.wait_group 1;");
        } else {
            asm volatile("cp.async.wait_group 0;");
        }
        __syncthreads();

        const float* Ab = &As[kt & 1][0];
        const float* Bb = &Bs[kt & 1][0];

        #pragma unroll
        for (int kf = 0; kf < 2; kf++) {
            const int kb = kf * 8;
            uint32_t ah[4][4], al[4][4];
            #pragma unroll
            for (int i = 0; i < 4; i++) {
                const float* ap = Ab + (warp_m * 64 + i * 16 + gr) * LDSP + kb + gc;
                split_tf32(ap[0],            ah[i][0], al[i][0]);
                split_tf32(ap[8 * LDSP],     ah[i][1], al[i][1]);
                split_tf32(ap[4],            ah[i][2], al[i][2]);
                split_tf32(ap[8 * LDSP + 4], ah[i][3], al[i][3]);
            }
            uint32_t bh[4][2], bl[4][2];
            #pragma unroll
            for (int j = 0; j < 4; j++) {
                const float* bp = Bb + (warp_n * 32 + j * 8 + gr) * LDSP + kb + gc;
                split_tf32(bp[0], bh[j][0], bl[j][0]);
                split_tf32(bp[4], bh[j][1], bl[j][1]);
            }
            #pragma unroll
            for (int i = 0; i < 4; i++)
                #pragma unroll
                for (int j = 0; j < 4; j++) {
                    mma_tf32(acc[i][j], al[i], bh[j]);   // lo*hi
                    mma_tf32(acc[i][j], ah[i], bl[j]);   // hi*lo
                    mma_tf32(acc[i][j], ah[i], bh[j]);   // hi*hi
                }
        }
        __syncthreads();
    }

    // epilogue
    #pragma unroll
    for (int i = 0; i < 4; i++) {
        const int row0 = bm + warp_m * 64 + i * 16 + gr;
        #pragma unroll
        for (int j = 0; j < 4; j++) {
            const int col = bn + warp_n * 32 + j * 8 + gc * 2;
            float2 v0 = make_float2(acc[i][j][0], acc[i][j][1]);
            float2 v1 = make_float2(acc[i][j][2], acc[i][j][3]);
            if (bias) {
                const float b0 = bias[col], b1 = bias[col + 1];
                v0.x += b0; v0.y += b1; v1.x += b0; v1.y += b1;
            }
            *reinterpret_cast<float2*>(C + (size_t)row0 * N + col) = v0;
            *reinterpret_cast<float2*>(C + (size_t)(row0 + 8) * N + col) = v1;
        }
    }
}

// ---------------- V row-sum (2-stage): S[bh,dh] = sum_n v[b,h,n,dh] ----------
__global__ void vsum_partial() {
    const int N = 2048, C3 = 3072, Dh = 64, H = 16;
    const int bh = blockIdx.x;          // 0..31
    const int s  = blockIdx.y;          // 0..15
    const int b = bh / H, h = bh % H;
    const int dh = threadIdx.x;         // 0..63
    const float* base = g_qkv + (size_t)(b * N) * C3 + 2048 + h * Dh + dh;
    float acc = 0.0f;
    const int n0 = s * 128;
    for (int n = n0; n < n0 + 128; n++) acc += base[(size_t)n * C3];
    g_vsum_p[(bh * 16 + s) * Dh + dh] = acc;
}

__global__ void vsum_reduce() {
    const int Dh = 64;
    const int bh = blockIdx.x;
    const int dh = threadIdx.x;
    float acc = 0.0f;
    #pragma unroll
    for (int s = 0; s < 16; s++) acc += g_vsum_p[(bh * 16 + s) * Dh + dh];
    g_vsum[bh * Dh + dh] = acc;
}

// ---------------- banded attention (one warp per (b,h,n)) -------------------
__global__ void band_attn(const int* __restrict__ epoch_p) {
    const int N = 2048, H = 16, Dh = 64, C3 = 3072;
    const int w = (*epoch_p < 15) ? 16 : 20;

    const int warp = (blockIdx.x * blockDim.x + threadIdx.x) >> 5;
    const int lane = threadIdx.x & 31;
    if (warp >= 2 * H * N) return;

    const int n  = warp % N;
    const int bh = warp / N;
    const int b  = bh / H, h = bh % H;

    const float* qp = g_qkv + (size_t)(b * N + n) * C3 + h * Dh;
    const float q0 = qp[lane], q1 = qp[lane + 32];

    const int m0 = max(0, n - w);
    const int m1 = min(N - 1, n + w);

    float Mx = -INFINITY, Z = 0.0f;
    float a0 = 0.0f, a1 = 0.0f, bv0 = 0.0f, bv1 = 0.0f;

    for (int m = m0; m <= m1; m++) {
        const float* kp = g_qkv + (size_t)(b * N + m) * C3 + 1024 + h * Dh;
        const float k0 = kp[lane], k1 = kp[lane + 32];
        const float v0 = kp[1024 + lane], v1 = kp[1024 + lane + 32];

        float p = q0 * k0 + q1 * k1;
        p += __shfl_xor_sync(0xffffffffu, p, 16);
        p += __shfl_xor_sync(0xffffffffu, p, 8);
        p += __shfl_xor_sync(0xffffffffu, p, 4);
        p += __shfl_xor_sync(0xffffffffu, p, 2);
        p += __shfl_xor_sync(0xffffffffu, p, 1);
        const float l = p * 4.0f;   // scale = Dh // H = 4

        if (l > Mx) {
            const float f = expf(Mx - l);
            Z *= f; a0 *= f; a1 *= f;
            Mx = l;
        }
        const float e = expf(l - Mx);
        Z += e;
        a0 = fmaf(e, v0, a0);
        a1 = fmaf(e, v1, a1);
        bv0 += v0; bv1 += v1;
    }

    float lm = 1e-9f;
    if (lm > Mx) {
        const float f = expf(Mx - lm);
        Z *= f; a0 *= f; a1 *= f;
        Mx = lm;
    }
    const float cu = expf(lm - Mx);
    const int nband = m1 - m0 + 1;
    Z += (float)(N - nband) * cu;

    const float s0 = g_vsum[bh * Dh + lane];
    const float s1 = g_vsum[bh * Dh + lane + 32];
    const float invZ = 1.0f / Z;
    const float o0 = (a0 + cu * (s0 - bv0)) * invZ;
    const float o1 = (a1 + cu * (s1 - bv1)) * invZ;

    float* op = g_att + (size_t)(b * N + n) * 1024 + h * Dh;
    op[lane]      = o0;
    op[lane + 32] = o1;
}

// ---------------- launcher ---------------------------------------------------
extern "C" void kernel_launch(void* const* d_in, const int* in_sizes, int n_in,
                              void* d_out, int out_size) {
    const float* x      = (const float*)d_in[0];   // [2,2048,1024]
    const float* qkv_w  = (const float*)d_in[1];   // [3072,1024]
    const float* proj_w = (const float*)d_in[2];   // [1024,1024]
    const float* proj_b = (const float*)d_in[3];   // [1024]
    const int*   epoch  = (const int*)d_in[4];     // scalar

    float* qkv_buf; float* att_buf;
    cudaGetSymbolAddress((void**)&qkv_buf, g_qkv);
    cudaGetSymbolAddress((void**)&att_buf, g_att);

    const int M = 4096, K = 1024;

    // 1) qkv = x @ qkv_w^T -> [4096, 3072]
    {
        dim3 grid(3072 / 128, M / 128);
        gemm_3xtf32<<<grid, 256>>>(x, qkv_w, nullptr, qkv_buf, M, 3072, K);
    }

    // 2) V row sums (2-stage)
    {
        dim3 g1(32, 16);
        vsum_partial<<<g1, 64>>>();
        vsum_reduce<<<32, 64>>>();
    }

    // 3) banded attention -> g_att
    {
        const int total_warps = 2 * 16 * 2048;
        band_attn<<<total_warps / 8, 256>>>(epoch);
    }

    // 4) out = att @ proj_w^T + proj_b -> d_out
    {
        dim3 grid(1024 / 128, M / 128);
        gemm_3xtf32<<<grid, 256>>>(att_buf, proj_w, proj_b, (float*)d_out, M, 1024, K);
    }
}

// round 5
// speedup vs baseline: 4.0788x; 3.0410x over previous
#include <cuda_runtime.h>
#include <cuda_bf16.h>
#include <cstdint>
#include <math.h>

// ---------------- scratch (static device globals; no runtime alloc) ----------
__device__ float g_qkv[2 * 2048 * 3072];        // [B,N,3C] fp32
__device__ float g_vsum[32 * 64];
__device__ float g_vsum_p[32 * 16 * 64];
__device__ __nv_bfloat16 g_xh[4096 * 1024], g_xl[4096 * 1024];
__device__ __nv_bfloat16 g_w1h[3072 * 1024], g_w1l[3072 * 1024];
__device__ __nv_bfloat16 g_w2h[1024 * 1024], g_w2l[1024 * 1024];
__device__ __nv_bfloat16 g_ah[4096 * 1024], g_al[4096 * 1024];
__device__ int g_tc_ok;     // set by tcgen05 kernel if that code path exists

// ---------------- helpers -----------------------------------------------------
__device__ __forceinline__ unsigned short bfbits(__nv_bfloat16 v) {
    return *reinterpret_cast<unsigned short*>(&v);
}

// ---------------- fp32 -> bf16 hi/lo split -----------------------------------
__global__ void split_kernel(const float* __restrict__ src,
                             __nv_bfloat16* __restrict__ hi,
                             __nv_bfloat16* __restrict__ lo, int n4) {
    int i = blockIdx.x * 256 + threadIdx.x;
    if (i >= n4) return;
    float4 v = reinterpret_cast<const float4*>(src)[i];
    float vv[4] = {v.x, v.y, v.z, v.w};
    unsigned short hb[4], lb[4];
    #pragma unroll
    for (int j = 0; j < 4; j++) {
        __nv_bfloat16 h = __float2bfloat16_rn(vv[j]);
        __nv_bfloat16 l = __float2bfloat16_rn(vv[j] - __bfloat162float(h));
        hb[j] = bfbits(h); lb[j] = bfbits(l);
    }
    reinterpret_cast<ushort4*>(hi)[i] = make_ushort4(hb[0], hb[1], hb[2], hb[3]);
    reinterpret_cast<ushort4*>(lo)[i] = make_ushort4(lb[0], lb[1], lb[2], lb[3]);
}

// =============================================================================
// Path A: tcgen05 GEMM (compiled only for sm_103a feature set)
// =============================================================================
#define TILE_BYTES 16384            // 128 rows * 128 bytes (SW128)
#define GEMM_TC_SMEM (2048 + 1024 + 8 * TILE_BYTES)

#if defined(__CUDA_ARCH__) && defined(__CUDA_ARCH_FEAT_SM103_ALL)
__device__ __forceinline__ uint32_t elect1() {
    uint32_t p;
    asm volatile("{\n\t.reg .pred p;\n\telect.sync _|p, 0xFFFFFFFF;\n\tselp.b32 %0,1,0,p;\n\t}"
                 : "=r"(p));
    return p;
}
__device__ __forceinline__ uint64_t make_desc_sw128(uint32_t addr) {
    return ((uint64_t)2 << 61) | ((uint64_t)1 << 46) | ((uint64_t)64 << 32) |
           ((uint64_t)1 << 16) | (uint64_t)((addr >> 4) & 0x3FFF);
}
__device__ __forceinline__ void mma_f16_ss(uint32_t d, uint64_t a, uint64_t b,
                                           uint32_t idesc, uint32_t acc) {
    asm volatile(
        "{\n\t.reg .pred p;\n\tsetp.ne.u32 p, %4, 0;\n\t"
        "tcgen05.mma.cta_group::1.kind::f16 [%0], %1, %2, %3, {%5,%5,%5,%5}, p;\n\t}"
        :: "r"(d), "l"(a), "l"(b), "r"(idesc), "r"(acc), "r"(0u) : "memory");
}
#define MBAR_INIT(a, c) \
    asm volatile("mbarrier.init.shared.b64 [%0], %1;" :: "r"(a), "r"(c) : "memory")
#define MBAR_WAIT(a, ph) do {                                                   \
    uint32_t _done = 0;                                                         \
    while (!_done) {                                                            \
        asm volatile(                                                           \
            "{\n\t.reg .pred p;\n\t"                                            \
            "mbarrier.try_wait.parity.acquire.cta.shared::cta.b64 p, [%1], %2, 0x989680;\n\t" \
            "selp.b32 %0,1,0,p;\n\t}"                                           \
            : "=r"(_done) : "r"(a), "r"((uint32_t)(ph)) : "memory");            \
    }                                                                           \
} while (0)
#define TC_COMMIT(mb) \
    asm volatile("tcgen05.commit.cta_group::1.mbarrier::arrive::one.shared::cluster.b64 [%0];" \
                 :: "r"(mb) : "memory")
#define TC_LD_X32(r, addr)                                                      \
    asm volatile("tcgen05.ld.sync.aligned.32x32b.x32.b32 "                      \
        "{%0,%1,%2,%3,%4,%5,%6,%7,%8,%9,%10,%11,%12,%13,%14,%15,"              \
        "%16,%17,%18,%19,%20,%21,%22,%23,%24,%25,%26,%27,%28,%29,%30,%31}, [%32];" \
        : "=r"((r)[0]),"=r"((r)[1]),"=r"((r)[2]),"=r"((r)[3]),                  \
          "=r"((r)[4]),"=r"((r)[5]),"=r"((r)[6]),"=r"((r)[7]),                  \
          "=r"((r)[8]),"=r"((r)[9]),"=r"((r)[10]),"=r"((r)[11]),                \
          "=r"((r)[12]),"=r"((r)[13]),"=r"((r)[14]),"=r"((r)[15]),              \
          "=r"((r)[16]),"=r"((r)[17]),"=r"((r)[18]),"=r"((r)[19]),              \
          "=r"((r)[20]),"=r"((r)[21]),"=r"((r)[22]),"=r"((r)[23]),              \
          "=r"((r)[24]),"=r"((r)[25]),"=r"((r)[26]),"=r"((r)[27]),              \
          "=r"((r)[28]),"=r"((r)[29]),"=r"((r)[30]),"=r"((r)[31])               \
        : "r"(addr))
#endif

__global__ __launch_bounds__(128, 1)
void gemm_tc(const __nv_bfloat16* __restrict__ Ah_, const __nv_bfloat16* __restrict__ Al_,
             const __nv_bfloat16* __restrict__ Bh_, const __nv_bfloat16* __restrict__ Bl_,
             const float* __restrict__ bias, float* __restrict__ C, int N, int K) {
#if defined(__CUDA_ARCH__) && defined(__CUDA_ARCH_FEAT_SM103_ALL)
    extern __shared__ char smem[];
    const int tid = threadIdx.x;
    if (tid == 0) g_tc_ok = 1;
    const int bm = blockIdx.y * 128, bn = blockIdx.x * 128;
    const uint32_t sbase = (uint32_t)__cvta_generic_to_shared(smem);
    const uint32_t tiles0 = (sbase + 2048 + 1023) & ~1023u;   // 1024-aligned tiles
    const uint32_t mb0 = sbase + 8, mb1 = sbase + 16;

    if (tid == 0) { MBAR_INIT(mb0, 1); MBAR_INIT(mb1, 1); }
    if (tid < 32) {
        asm volatile("tcgen05.alloc.cta_group::1.sync.aligned.shared::cta.b32 [%0], %1;"
                     :: "r"(sbase), "r"(128u) : "memory");
    }
    __syncthreads();
    uint32_t tmem;
    asm volatile("ld.shared.b32 %0, [%1];" : "=r"(tmem) : "r"(sbase));

    const __nv_bfloat16* srcs[4] = {
        Ah_ + (size_t)bm * K, Al_ + (size_t)bm * K,
        Bh_ + (size_t)bn * K, Bl_ + (size_t)bn * K };

    auto load_stage = [&](int s, int k0) {
        #pragma unroll
        for (int t = 0; t < 4; t++) {
            const __nv_bfloat16* bp = srcs[t] + k0;
            const uint32_t tb = tiles0 + (uint32_t)(s * 4 + t) * TILE_BYTES;
            #pragma unroll
            for (int i = 0; i < 8; i++) {
                const int cid = tid + i * 128;          // 0..1023
                const int row = cid >> 3, c16 = cid & 7;
                uint32_t off = (uint32_t)row * 128 + (uint32_t)c16 * 16;
                uint32_t sw = off ^ ((off >> 3) & 0x70);
                asm volatile("cp.async.ca.shared.global [%0], [%1], 16;"
                             :: "r"(tb + sw), "l"(bp + (size_t)row * K + c16 * 8));
            }
        }
        asm volatile("cp.async.commit_group;");
    };

    const int nkt = K >> 6;
    int phase0 = 0, phase1 = 0;
    load_stage(0, 0);

    const uint32_t idesc = 0x8200490u;   // f32 d, bf16 a/b, M=128, N=128

    for (int kt = 0; kt < nkt; kt++) {
        const int s = kt & 1;
        if (kt >= 1) {   // stage s^1 about to be overwritten; wait chunk kt-1 MMAs
            if (s == 0) { MBAR_WAIT(mb1, phase1); phase1 ^= 1; }
            else        { MBAR_WAIT(mb0, phase0); phase0 ^= 1; }
        }
        if (kt + 1 < nkt) {
            load_stage(s ^ 1, (kt + 1) * 64);
            asm volatile("cp.async.wait_group 1;");
        } else {
            asm volatile("cp.async.wait_group 0;");
        }
        __syncthreads();

        if (tid < 32 && elect1()) {
            asm volatile("fence.proxy.async.shared::cta;" ::: "memory");
            const uint32_t base = tiles0 + (uint32_t)(s * 4) * TILE_BYTES;
            const uint64_t dAh = make_desc_sw128(base);
            const uint64_t dAl = make_desc_sw128(base + TILE_BYTES);
            const uint64_t dBh = make_desc_sw128(base + 2 * TILE_BYTES);
            const uint64_t dBl = make_desc_sw128(base + 3 * TILE_BYTES);
            #pragma unroll
            for (int k = 0; k < 4; k++) {
                const uint32_t acc0 = (kt == 0 && k == 0) ? 0u : 1u;
                mma_f16_ss(tmem, dAh + k * 2, dBh + k * 2, idesc, acc0);
                mma_f16_ss(tmem, dAh + k * 2, dBl + k * 2, idesc, 1u);
                mma_f16_ss(tmem, dAl + k * 2, dBh + k * 2, idesc, 1u);
            }
            TC_COMMIT(s == 0 ? mb0 : mb1);
        }
    }
    {
        const int s = (nkt - 1) & 1;
        if (s == 0) { MBAR_WAIT(mb0, phase0); }
        else        { MBAR_WAIT(mb1, phase1); }
    }
    asm volatile("tcgen05.fence::after_thread_sync;" ::: "memory");

    const int wid = tid >> 5, lane = tid & 31;
    const int row = bm + wid * 32 + lane;
    float* Cr = C + (size_t)row * N + bn;
    #pragma unroll
    for (int g = 0; g < 4; g++) {
        uint32_t r[32];
        TC_LD_X32(r, tmem + g * 32);
        asm volatile("tcgen05.wait::ld.sync.aligned;" ::: "memory");
        #pragma unroll
        for (int j = 0; j < 32; j += 4) {
            float4 o;
            o.x = __uint_as_float(r[j + 0]);
            o.y = __uint_as_float(r[j + 1]);
            o.z = __uint_as_float(r[j + 2]);
            o.w = __uint_as_float(r[j + 3]);
            if (bias) {
                const float4 b4 = *reinterpret_cast<const float4*>(bias + bn + g * 32 + j);
                o.x += b4.x; o.y += b4.y; o.z += b4.z; o.w += b4.w;
            }
            *reinterpret_cast<float4*>(Cr + g * 32 + j) = o;
        }
    }
    asm volatile("tcgen05.fence::before_thread_sync;" ::: "memory");
    __syncthreads();
    if (tid < 32) {
        asm volatile("tcgen05.relinquish_alloc_permit.cta_group::1.sync.aligned;");
        asm volatile("tcgen05.dealloc.cta_group::1.sync.aligned.b32 %0, %1;"
                     :: "r"(tmem), "r"(128u));
    }
#endif
}

// =============================================================================
// Path B: fallback — 3xBF16 mma.sync.m16n8k16 (baseline compute_103 safe)
// Skips itself if the tcgen05 path ran.
// =============================================================================
#define MSTRIDE 20                   // u32 per smem row (32 bf16 + pad)
#define MTILE_U32 (128 * MSTRIDE)    // 2560 u32 per tile
#define GEMM_MMA_SMEM (8 * MTILE_U32 * 4)   // 81920 B

__device__ __forceinline__ void mma_bf16(float* c, const uint32_t* a, const uint32_t* b) {
    asm volatile(
        "mma.sync.aligned.m16n8k16.row.col.f32.bf16.bf16.f32 "
        "{%0,%1,%2,%3}, {%4,%5,%6,%7}, {%8,%9}, {%0,%1,%2,%3};"
        : "+f"(c[0]), "+f"(c[1]), "+f"(c[2]), "+f"(c[3])
        : "r"(a[0]), "r"(a[1]), "r"(a[2]), "r"(a[3]), "r"(b[0]), "r"(b[1]));
}

__global__ __launch_bounds__(256)
void gemm_mma(const __nv_bfloat16* __restrict__ Ah_, const __nv_bfloat16* __restrict__ Al_,
              const __nv_bfloat16* __restrict__ Bh_, const __nv_bfloat16* __restrict__ Bl_,
              const float* __restrict__ bias, float* __restrict__ C, int N, int K) {
    if (*(volatile int*)&g_tc_ok) return;
    extern __shared__ uint32_t sm_u[];

    const int tid = threadIdx.x;
    const int lane = tid & 31;
    const int wid = tid >> 5;
    const int warp_m = wid & 1;    // 2 x 64 rows
    const int warp_n = wid >> 1;   // 4 x 32 cols
    const int bm = blockIdx.y * 128;
    const int bn = blockIdx.x * 128;
    const int gr = lane >> 2;      // 0..7
    const int gc = lane & 3;       // 0..3

    const __nv_bfloat16* srcs[4] = {
        Ah_ + (size_t)bm * K, Al_ + (size_t)bm * K,
        Bh_ + (size_t)bn * K, Bl_ + (size_t)bn * K };

    float acc[4][4][4];
    #pragma unroll
    for (int i = 0; i < 4; i++)
        #pragma unroll
        for (int j = 0; j < 4; j++)
            #pragma unroll
            for (int r = 0; r < 4; r++) acc[i][j][r] = 0.0f;

    auto load_stage = [&](int s, int k0) {
        #pragma unroll
        for (int i = 0; i < 8; i++) {
            const int cid = tid + i * 256;        // 0..2047
            const int t = cid >> 9;               // tile 0..3
            const int c = cid & 511;
            const int row = c >> 2, c16 = c & 3;  // 4 x 16B per 64B row
            uint32_t daddr = (uint32_t)__cvta_generic_to_shared(
                sm_u + (s * 4 + t) * MTILE_U32 + row * MSTRIDE + c16 * 4);
            asm volatile("cp.async.ca.shared.global [%0], [%1], 16;"
                         :: "r"(daddr), "l"(srcs[t] + (size_t)row * K + k0 + c16 * 8));
        }
        asm volatile("cp.async.commit_group;");
    };

    const int nkt = K >> 5;     // K/32
    load_stage(0, 0);

    for (int kt = 0; kt < nkt; kt++) {
        const int s = kt & 1;
        if (kt + 1 < nkt) {
            load_stage(s ^ 1, (kt + 1) * 32);
            asm volatile("cp.async.wait_group 1;");
        } else {
            asm volatile("cp.async.wait_group 0;");
        }
        __syncthreads();

        const uint32_t* Abh = sm_u + (s * 4 + 0) * MTILE_U32;
        const uint32_t* Abl = sm_u + (s * 4 + 1) * MTILE_U32;
        const uint32_t* Bbh = sm_u + (s * 4 + 2) * MTILE_U32;
        const uint32_t* Bbl = sm_u + (s * 4 + 3) * MTILE_U32;

        #pragma unroll
        for (int ks = 0; ks < 2; ks++) {
            const int kb = ks * 8;
            uint32_t ah[4][4], al[4][4];
            #pragma unroll
            for (int i = 0; i < 4; i++) {
                const int base = (warp_m * 64 + i * 16 + gr) * MSTRIDE + kb + gc;
                ah[i][0] = Abh[base];           ah[i][1] = Abh[base + 8 * MSTRIDE];
                ah[i][2] = Abh[base + 4];       ah[i][3] = Abh[base + 8 * MSTRIDE + 4];
                al[i][0] = Abl[base];           al[i][1] = Abl[base + 8 * MSTRIDE];
                al[i][2] = Abl[base + 4];       al[i][3] = Abl[base + 8 * MSTRIDE + 4];
            }
            uint32_t bh[4][2], bl[4][2];
            #pragma unroll
            for (int j = 0; j < 4; j++) {
                const int bb = (warp_n * 32 + j * 8 + gr) * MSTRIDE + kb + gc;
                bh[j][0] = Bbh[bb];  bh[j][1] = Bbh[bb + 4];
                bl[j][0] = Bbl[bb];  bl[j][1] = Bbl[bb + 4];
            }
            #pragma unroll
            for (int i = 0; i < 4; i++)
                #pragma unroll
                for (int j = 0; j < 4; j++) {
                    mma_bf16(acc[i][j], ah[i], bh[j]);
                    mma_bf16(acc[i][j], ah[i], bl[j]);
                    mma_bf16(acc[i][j], al[i], bh[j]);
                }
        }
        __syncthreads();
    }

    #pragma unroll
    for (int i = 0; i < 4; i++) {
        const int row0 = bm + warp_m * 64 + i * 16 + gr;
        #pragma unroll
        for (int j = 0; j < 4; j++) {
            const int col = bn + warp_n * 32 + j * 8 + gc * 2;
            float2 v0 = make_float2(acc[i][j][0], acc[i][j][1]);
            float2 v1 = make_float2(acc[i][j][2], acc[i][j][3]);
            if (bias) {
                const float b0 = bias[col], b1 = bias[col + 1];
                v0.x += b0; v0.y += b1; v1.x += b0; v1.y += b1;
            }
            *reinterpret_cast<float2*>(C + (size_t)row0 * N + col) = v0;
            *reinterpret_cast<float2*>(C + (size_t)(row0 + 8) * N + col) = v1;
        }
    }
}

// ---------------- V row-sum (2-stage) ----------------------------------------
__global__ void vsum_partial() {
    const int N = 2048, C3 = 3072, Dh = 64, H = 16;
    const int bh = blockIdx.x, s = blockIdx.y;
    const int b = bh / H, h = bh % H;
    const int dh = threadIdx.x;
    const float* base = g_qkv + (size_t)(b * N) * C3 + 2048 + h * Dh + dh;
    float acc = 0.0f;
    const int n0 = s * 128;
    for (int n = n0; n < n0 + 128; n++) acc += base[(size_t)n * C3];
    g_vsum_p[(bh * 16 + s) * Dh + dh] = acc;
}
__global__ void vsum_reduce() {
    const int Dh = 64;
    const int bh = blockIdx.x, dh = threadIdx.x;
    float acc = 0.0f;
    #pragma unroll
    for (int s = 0; s < 16; s++) acc += g_vsum_p[(bh * 16 + s) * Dh + dh];
    g_vsum[bh * Dh + dh] = acc;
}

// ---------------- banded attention (one warp per (b,h,n)); emits bf16 hi/lo --
__global__ void band_attn(const int* __restrict__ epoch_p) {
    const int N = 2048, H = 16, Dh = 64, C3 = 3072;
    const int w = (*epoch_p < 15) ? 16 : 20;

    const int warp = (blockIdx.x * blockDim.x + threadIdx.x) >> 5;
    const int lane = threadIdx.x & 31;
    if (warp >= 2 * H * N) return;

    const int n  = warp % N;
    const int bh = warp / N;
    const int b  = bh / H, h = bh % H;

    const float* qp = g_qkv + (size_t)(b * N + n) * C3 + h * Dh;
    const float q0 = qp[lane], q1 = qp[lane + 32];
    const float s0 = g_vsum[bh * Dh + lane];
    const float s1 = g_vsum[bh * Dh + lane + 32];

    const int m0 = max(0, n - w);
    const int m1 = min(N - 1, n + w);

    float Mx = -INFINITY, Z = 0.0f;
    float a0 = 0.0f, a1 = 0.0f, bv0 = 0.0f, bv1 = 0.0f;

    const float* kp = g_qkv + (size_t)(b * N + m0) * C3 + 1024 + h * Dh;
    for (int m = m0; m <= m1; m++, kp += C3) {
        const float k0 = kp[lane], k1 = kp[lane + 32];
        const float v0 = kp[1024 + lane], v1 = kp[1024 + lane + 32];

        float p = q0 * k0 + q1 * k1;
        p += __shfl_xor_sync(0xffffffffu, p, 16);
        p += __shfl_xor_sync(0xffffffffu, p, 8);
        p += __shfl_xor_sync(0xffffffffu, p, 4);
        p += __shfl_xor_sync(0xffffffffu, p, 2);
        p += __shfl_xor_sync(0xffffffffu, p, 1);
        const float l = p * 4.0f;   // scale = Dh // H = 4

        if (l > Mx) {
            const float f = __expf(Mx - l);
            Z *= f; a0 *= f; a1 *= f;
            Mx = l;
        }
        const float e = __expf(l - Mx);
        Z += e;
        a0 = fmaf(e, v0, a0);
        a1 = fmaf(e, v1, a1);
        bv0 += v0; bv1 += v1;
    }

    const float lm = 1e-9f;
    const float cu = __expf(lm - Mx);
    const int nband = m1 - m0 + 1;
    Z += (float)(N - nband) * cu;

    const float invZ = 1.0f / Z;
    const float o0 = (a0 + cu * (s0 - bv0)) * invZ;
    const float o1 = (a1 + cu * (s1 - bv1)) * invZ;

    const size_t idx = (size_t)(b * N + n) * 1024 + h * Dh;
    __nv_bfloat16 h0 = __float2bfloat16_rn(o0);
    __nv_bfloat16 l0 = __float2bfloat16_rn(o0 - __bfloat162float(h0));
    __nv_bfloat16 h1 = __float2bfloat16_rn(o1);
    __nv_bfloat16 l1 = __float2bfloat16_rn(o1 - __bfloat162float(h1));
    g_ah[idx + lane] = h0;  g_al[idx + lane] = l0;
    g_ah[idx + lane + 32] = h1;  g_al[idx + lane + 32] = l1;
}

// ---------------- launcher ---------------------------------------------------
extern "C" void kernel_launch(void* const* d_in, const int* in_sizes, int n_in,
                              void* d_out, int out_size) {
    const float* x      = (const float*)d_in[0];
    const float* qkv_w  = (const float*)d_in[1];
    const float* proj_w = (const float*)d_in[2];
    const float* proj_b = (const float*)d_in[3];
    const int*   epoch  = (const int*)d_in[4];

    float* qkv_buf;
    __nv_bfloat16 *xh, *xl, *w1h, *w1l, *w2h, *w2l, *ah, *al;
    cudaGetSymbolAddress((void**)&qkv_buf, g_qkv);
    cudaGetSymbolAddress((void**)&xh, g_xh);   cudaGetSymbolAddress((void**)&xl, g_xl);
    cudaGetSymbolAddress((void**)&w1h, g_w1h); cudaGetSymbolAddress((void**)&w1l, g_w1l);
    cudaGetSymbolAddress((void**)&w2h, g_w2h); cudaGetSymbolAddress((void**)&w2l, g_w2l);
    cudaGetSymbolAddress((void**)&ah, g_ah);   cudaGetSymbolAddress((void**)&al, g_al);

    cudaFuncSetAttribute(gemm_tc, cudaFuncAttributeMaxDynamicSharedMemorySize, GEMM_TC_SMEM);
    cudaFuncSetAttribute(gemm_mma, cudaFuncAttributeMaxDynamicSharedMemorySize, GEMM_MMA_SMEM);

    // 1) split inputs to bf16 hi/lo
    {
        int n4 = 4096 * 1024 / 4;
        split_kernel<<<(n4 + 255) / 256, 256>>>(x, xh, xl, n4);
        n4 = 3072 * 1024 / 4;
        split_kernel<<<(n4 + 255) / 256, 256>>>(qkv_w, w1h, w1l, n4);
        n4 = 1024 * 1024 / 4;
        split_kernel<<<(n4 + 255) / 256, 256>>>(proj_w, w2h, w2l, n4);
    }

    // 2) qkv = x @ qkv_w^T : tcgen05 if available, else mma.sync fallback
    gemm_tc<<<dim3(3072 / 128, 4096 / 128), 128, GEMM_TC_SMEM>>>(
        xh, xl, w1h, w1l, nullptr, qkv_buf, 3072, 1024);
    gemm_mma<<<dim3(3072 / 128, 4096 / 128), 256, GEMM_MMA_SMEM>>>(
        xh, xl, w1h, w1l, nullptr, qkv_buf, 3072, 1024);

    // 3) V row sums
    {
        dim3 g1(32, 16);
        vsum_partial<<<g1, 64>>>();
        vsum_reduce<<<32, 64>>>();
    }

    // 4) banded attention -> bf16 hi/lo att
    band_attn<<<(2 * 16 * 2048) / 8, 256>>>(epoch);

    // 5) out = att @ proj_w^T + proj_b
    gemm_tc<<<dim3(1024 / 128, 4096 / 128), 128, GEMM_TC_SMEM>>>(
        ah, al, w2h, w2l, proj_b, (float*)d_out, 1024, 1024);
    gemm_mma<<<dim3(1024 / 128, 4096 / 128), 256, GEMM_MMA_SMEM>>>(
        ah, al, w2h, w2l, proj_b, (float*)d_out, 1024, 1024);
}